// round 15
// baseline (speedup 1.0000x reference)
#include <cuda_runtime.h>
#include <cuda_fp16.h>
#include <math.h>

#define B_  64
#define M_  16
#define A_  128
#define H_  128
#define P_  16
#define NATOM 100
#define NFP   2048
#define NTAB  (NATOM + NFP)     // 2148
#define RPB   16                // table rows per block in proj kernel
#define PROJ_GRID 135           // 7 atom blocks + 128 fp blocks (one wave)

// Dynamic smem layout for proj (floats):
//   s_W  [0, 16384)          64 KB  W-half, staged coalesced
//   s_eT [16384, 18432)       8 KB  E tile transposed [d][r], stride 16
//   s_p  [18432, 26624)      32 KB  K-slice partials [ks][r][h]
#define PROJ_SMEM_BYTES (26624 * 4)

// Scratch (__device__ globals: allocation-free rule)
__device__ __half g_proj_h[NTAB * H_];    // projected tables, fp16 (0.55 MB, L2-resident)
__device__ float  g_mol[B_ * M_ * H_];    // per-molecule mean embeddings

// ---------------------------------------------------------------------------
// Kernel 1: projected tables -> g_proj_h (fp16).  (R12 form — best measured)
// ---------------------------------------------------------------------------
__global__ __launch_bounds__(1024, 1)
void proj_kernel(const float* __restrict__ atom_emb,
                 const float* __restrict__ fp_emb,
                 const float* __restrict__ W_in,
                 const float* __restrict__ b_in) {
    extern __shared__ __align__(16) float smem[];
    float* s_W  = smem;              // [d][h] 128x128
    float* s_eT = smem + 16384;      // [d][r] stride 16
    float* s_p  = smem + 18432;      // [ks][r][h]

    const int tid = threadIdx.x;
    const int blk = blockIdx.x;
    const int h  = tid & 127;
    const int ks = (tid >> 7) & 3;
    const int rh = tid >> 9;
    const int r0 = rh * 8;
    const bool is_atom = (blk < 7);
    const int lrow0 = is_atom ? blk * RPB : (blk - 7) * RPB;
    const int nrows = is_atom ? NATOM : NFP;
    const float* __restrict__ Whalf = W_in + (is_atom ? 0 : H_ * H_);

    #pragma unroll
    for (int i = tid; i < 4096; i += 1024)
        ((float4*)s_W)[i] = ((const float4*)Whalf)[i];

    #pragma unroll
    for (int i = tid; i < RPB * H_; i += 1024) {
        int r = i >> 7, d = i & 127;
        int t = lrow0 + r;
        float v = 0.0f;
        if (t < nrows) v = is_atom ? atom_emb[t * H_ + d] : fp_emb[t * H_ + d];
        s_eT[d * 16 + r] = v;
    }
    __syncthreads();

    const int d0 = ks * 32;
    float acc[8];
    #pragma unroll
    for (int r = 0; r < 8; r++) acc[r] = 0.0f;

    #pragma unroll 8
    for (int dd = 0; dd < 32; dd++) {
        const int d = d0 + dd;
        const float w = s_W[d * H_ + h];                  // LDS.32, conflict-free
        const float* e = s_eT + d * 16 + r0;              // broadcast
        const float4 e0 = *(const float4*)(e);
        const float4 e1 = *(const float4*)(e + 4);
        acc[0] += e0.x * w; acc[1] += e0.y * w; acc[2] += e0.z * w; acc[3] += e0.w * w;
        acc[4] += e1.x * w; acc[5] += e1.y * w; acc[6] += e1.z * w; acc[7] += e1.w * w;
    }

    #pragma unroll
    for (int r = 0; r < 8; r++) s_p[(ks * RPB + r0 + r) * H_ + h] = acc[r];
    __syncthreads();

    const int NP = RPB * H_;
    #pragma unroll
    for (int i = tid; i < NP; i += 1024) {
        int r = i >> 7, hc = i & 127;
        int t = lrow0 + r;
        if (t < nrows) {
            float v = s_p[i] + s_p[NP + i] + s_p[2 * NP + i] + s_p[3 * NP + i];
            if (is_atom) g_proj_h[t * H_ + hc] = __float2half(v + b_in[hc]);
            else         g_proj_h[(NATOM + t) * H_ + hc] = __float2half(v);
        }
    }
}

// ---------------------------------------------------------------------------
// Kernel 2: per-molecule mean of relu(A_proj[af] + F_proj[fp]).
// Grid 512 x 256: 2 molecules/block, 8 warps, 32 atoms/warp.
// NEW: explicit 8-atom load batches (16 LDG.64 in flight per thread) to fix
// the MLP starvation seen at regs=32. No min-blocks clamp on registers.
// ---------------------------------------------------------------------------
__global__ __launch_bounds__(256)
void mol_kernel(const int* __restrict__ atom_features,
                const int* __restrict__ fingerprints) {
    __shared__ __align__(16) float s_part[8 * H_];

    const int tid  = threadIdx.x;
    const int w    = tid >> 5;                            // 0..7
    const int lane = tid & 31;
    const int ml   = w >> 2;                              // molecule-in-block 0..1
    const int q    = w & 3;                               // atom quarter
    const int bm   = blockIdx.x * 2 + ml;

    const int abase = bm * A_ + q * 32 + lane;
    const int ra = atom_features[abase] * (H_ / 4);       // uint2-row base
    const int rf = (NATOM + fingerprints[abase]) * (H_ / 4);

    const uint2* __restrict__ gp = (const uint2*)g_proj_h;
    const __half2 zero2 = __float2half2_rn(0.0f);

    float4 acc = make_float4(0.0f, 0.0f, 0.0f, 0.0f);

    #pragma unroll
    for (int batch = 0; batch < 4; batch++) {
        // Issue 16 independent loads into register arrays (MLP=16).
        uint2 ba[8], bf[8];
        #pragma unroll
        for (int j = 0; j < 8; j++) {
            const int a = batch * 8 + j;
            int ia = __shfl_sync(0xFFFFFFFFu, ra, a);
            int If = __shfl_sync(0xFFFFFFFFu, rf, a);
            ba[j] = gp[ia + lane];
            bf[j] = gp[If + lane];
        }
        // Consume.
        #pragma unroll
        for (int j = 0; j < 8; j++) {
            __half2 va0 = *(__half2*)&ba[j].x, va1 = *(__half2*)&ba[j].y;
            __half2 vf0 = *(__half2*)&bf[j].x, vf1 = *(__half2*)&bf[j].y;
            __half2 s0 = __hmax2(__hadd2(va0, vf0), zero2);
            __half2 s1 = __hmax2(__hadd2(va1, vf1), zero2);
            float2 p0 = __half22float2(s0);
            float2 p1 = __half22float2(s1);
            acc.x += p0.x; acc.y += p0.y; acc.z += p1.x; acc.w += p1.y;
        }
    }
    ((float4*)s_part)[w * 32 + lane] = acc;               // STS.128, conflict-free
    __syncthreads();

    {
        int m = tid >> 7, d = tid & 127;
        float v = (s_part[(4 * m + 0) * H_ + d] + s_part[(4 * m + 1) * H_ + d] +
                   s_part[(4 * m + 2) * H_ + d] + s_part[(4 * m + 3) * H_ + d])
                  * (1.0f / (float)A_);
        g_mol[(blockIdx.x * 2 + m) * H_ + d] = v;
    }
}

// ---------------------------------------------------------------------------
// Kernel 3: mixing weights + phys mix + LayerNorm + 2-layer MLP head.
// One block per batch item; 256 threads (W1 GEMV 2-way K-split).  (R12 form)
// ---------------------------------------------------------------------------
__global__ __launch_bounds__(256)
void head_kernel(const float* __restrict__ phys,
                 const float* __restrict__ ratios,
                 const float* __restrict__ ln_g,
                 const float* __restrict__ ln_b,
                 const float* __restrict__ W1,
                 const float* __restrict__ b1,
                 const float* __restrict__ W2,
                 const float* __restrict__ b2,
                 float* __restrict__ out) {
    const int b   = blockIdx.x;
    const int tid = threadIdx.x;
    const int h   = tid & 127;
    const int ks  = tid >> 7;          // 0,1: K-split of the W1 GEMV

    __shared__ float s_w[M_];
    __shared__ float s_z[H_ + P_];
    __shared__ float s_zn[H_ + P_];
    __shared__ float s_red[8];
    __shared__ float s_t[2][H_];

    if (tid < M_) s_w[tid] = ratios[b * M_ + tid];
    __syncthreads();
    if (tid == 0) {
        float s = 0.0f;
        #pragma unroll
        for (int m = 0; m < M_; m++) s += s_w[m];
        float inv = 1.0f / (s + 1e-8f);
        #pragma unroll
        for (int m = 0; m < M_; m++) s_w[m] *= inv;
    }
    __syncthreads();

    if (tid < H_) {
        float acc = 0.0f;
        #pragma unroll
        for (int m = 0; m < M_; m++) acc += s_w[m] * g_mol[(b * M_ + m) * H_ + tid];
        s_z[tid] = acc;
        if (tid < P_) {
            float accp = 0.0f;
            #pragma unroll
            for (int m = 0; m < M_; m++) {
                float v = phys[(b * M_ + m) * P_ + tid];
                if (v != v) v = 0.0f;
                else if (isinf(v)) v = (v > 0.0f) ? 1000.0f : -1000.0f;
                accp += s_w[m] * v;
            }
            s_z[H_ + tid] = accp;
        }
    }
    __syncthreads();

    if (tid < H_) {
        float x  = s_z[tid];
        float x2 = x * x;
        if (tid < P_) { float e = s_z[H_ + tid]; x += e; x2 += e * e; }
        #pragma unroll
        for (int o = 16; o > 0; o >>= 1) {
            x  += __shfl_xor_sync(0xFFFFFFFFu, x,  o);
            x2 += __shfl_xor_sync(0xFFFFFFFFu, x2, o);
        }
        int warp = tid >> 5;
        if ((tid & 31) == 0) { s_red[warp] = x; s_red[4 + warp] = x2; }
    }
    __syncthreads();

    if (tid < H_) {
        float sum  = s_red[0] + s_red[1] + s_red[2] + s_red[3];
        float sum2 = s_red[4] + s_red[5] + s_red[6] + s_red[7];
        const float N = (float)(H_ + P_);
        float mu  = sum / N;
        float var = sum2 / N - mu * mu;
        float rstd = rsqrtf(var + 1e-5f);
        s_zn[tid] = (s_z[tid] - mu) * rstd * ln_g[tid] + ln_b[tid];
        if (tid < P_) s_zn[H_ + tid] = (s_z[H_ + tid] - mu) * rstd * ln_g[H_ + tid] + ln_b[H_ + tid];
    }
    __syncthreads();

    // W1 GEMV, 2-way K-split: ks=0 -> d in [0,72), ks=1 -> d in [72,144)
    {
        float t = (ks == 0) ? b1[h] : 0.0f;
        const int dlo = ks * 72;
        #pragma unroll 8
        for (int d = 0; d < 72; d++) t += s_zn[dlo + d] * W1[(dlo + d) * H_ + h];
        s_t[ks][h] = t;
    }
    __syncthreads();

    if (tid < H_) {
        float r = fmaxf(s_t[0][tid] + s_t[1][tid], 0.0f) * W2[tid];
        #pragma unroll
        for (int o = 16; o > 0; o >>= 1) r += __shfl_xor_sync(0xFFFFFFFFu, r, o);
        int warp = tid >> 5;
        if ((tid & 31) == 0) s_red[warp] = r;
    }
    __syncthreads();
    if (tid == 0) {
        float y = s_red[0] + s_red[1] + s_red[2] + s_red[3] + b2[0];
        if (y != y) y = 0.0f;
        else if (isinf(y)) y = (y > 0.0f) ? 3.4028234663852886e38f : -3.4028234663852886e38f;
        out[b] = y;
    }
}

extern "C" void kernel_launch(void* const* d_in, const int* in_sizes, int n_in,
                              void* d_out, int out_size) {
    const int*   atom_features = (const int*)  d_in[0];
    const int*   fingerprints  = (const int*)  d_in[1];
    const float* phys          = (const float*)d_in[2];
    const float* ratios        = (const float*)d_in[3];
    const float* atom_emb      = (const float*)d_in[4];
    const float* fp_emb        = (const float*)d_in[5];
    const float* W_in          = (const float*)d_in[6];
    const float* b_in          = (const float*)d_in[7];
    const float* ln_g          = (const float*)d_in[8];
    const float* ln_b          = (const float*)d_in[9];
    const float* W1            = (const float*)d_in[10];
    const float* b1            = (const float*)d_in[11];
    const float* W2            = (const float*)d_in[12];
    const float* b2            = (const float*)d_in[13];
    float* out = (float*)d_out;

    static int smem_configured = 0;
    if (!smem_configured) {
        cudaFuncSetAttribute(proj_kernel,
                             cudaFuncAttributeMaxDynamicSharedMemorySize,
                             PROJ_SMEM_BYTES);
        smem_configured = 1;
    }

    proj_kernel<<<PROJ_GRID, 1024, PROJ_SMEM_BYTES>>>(atom_emb, fp_emb, W_in, b_in);
    mol_kernel<<<512, 256>>>(atom_features, fingerprints);
    head_kernel<<<B_, 256>>>(phys, ratios, ln_g, ln_b, W1, b1, W2, b2, out);
}

// round 16
// speedup vs baseline: 1.4599x; 1.4599x over previous
#include <cuda_runtime.h>
#include <cuda_fp16.h>
#include <math.h>

#define B_  64
#define M_  16
#define A_  128
#define H_  128
#define P_  16
#define NATOM 100
#define NFP   2048
#define NTAB  (NATOM + NFP)     // 2148
#define RPB   16                // table rows per block in proj kernel
#define PROJ_GRID 135           // 7 atom blocks + 128 fp blocks (one wave)

// Dynamic smem layout for proj (floats):
//   s_W  [0, 16384)          64 KB  W-half, staged coalesced
//   s_eT [16384, 18432)       8 KB  E tile transposed [d][r], stride 16
//   s_p  [18432, 26624)      32 KB  K-slice partials [ks][r][h]
#define PROJ_SMEM_BYTES (26624 * 4)

// Scratch (__device__ globals: allocation-free rule)
__device__ __half g_proj_h[NTAB * H_];    // projected tables, fp16 (0.55 MB, L2-resident)
__device__ float  g_mol[B_ * M_ * H_];    // per-molecule mean embeddings

// ---------------------------------------------------------------------------
// Kernel 1: projected tables -> g_proj_h (fp16).  (R12 form — best measured)
// ---------------------------------------------------------------------------
__global__ __launch_bounds__(1024, 1)
void proj_kernel(const float* __restrict__ atom_emb,
                 const float* __restrict__ fp_emb,
                 const float* __restrict__ W_in,
                 const float* __restrict__ b_in) {
    extern __shared__ __align__(16) float smem[];
    float* s_W  = smem;              // [d][h] 128x128
    float* s_eT = smem + 16384;      // [d][r] stride 16
    float* s_p  = smem + 18432;      // [ks][r][h]

    const int tid = threadIdx.x;
    const int blk = blockIdx.x;
    const int h  = tid & 127;
    const int ks = (tid >> 7) & 3;
    const int rh = tid >> 9;
    const int r0 = rh * 8;
    const bool is_atom = (blk < 7);
    const int lrow0 = is_atom ? blk * RPB : (blk - 7) * RPB;
    const int nrows = is_atom ? NATOM : NFP;
    const float* __restrict__ Whalf = W_in + (is_atom ? 0 : H_ * H_);

    #pragma unroll
    for (int i = tid; i < 4096; i += 1024)
        ((float4*)s_W)[i] = ((const float4*)Whalf)[i];

    #pragma unroll
    for (int i = tid; i < RPB * H_; i += 1024) {
        int r = i >> 7, d = i & 127;
        int t = lrow0 + r;
        float v = 0.0f;
        if (t < nrows) v = is_atom ? atom_emb[t * H_ + d] : fp_emb[t * H_ + d];
        s_eT[d * 16 + r] = v;
    }
    __syncthreads();

    const int d0 = ks * 32;
    float acc[8];
    #pragma unroll
    for (int r = 0; r < 8; r++) acc[r] = 0.0f;

    #pragma unroll 8
    for (int dd = 0; dd < 32; dd++) {
        const int d = d0 + dd;
        const float w = s_W[d * H_ + h];                  // LDS.32, conflict-free
        const float* e = s_eT + d * 16 + r0;              // broadcast
        const float4 e0 = *(const float4*)(e);
        const float4 e1 = *(const float4*)(e + 4);
        acc[0] += e0.x * w; acc[1] += e0.y * w; acc[2] += e0.z * w; acc[3] += e0.w * w;
        acc[4] += e1.x * w; acc[5] += e1.y * w; acc[6] += e1.z * w; acc[7] += e1.w * w;
    }

    #pragma unroll
    for (int r = 0; r < 8; r++) s_p[(ks * RPB + r0 + r) * H_ + h] = acc[r];
    __syncthreads();

    const int NP = RPB * H_;
    #pragma unroll
    for (int i = tid; i < NP; i += 1024) {
        int r = i >> 7, hc = i & 127;
        int t = lrow0 + r;
        if (t < nrows) {
            float v = s_p[i] + s_p[NP + i] + s_p[2 * NP + i] + s_p[3 * NP + i];
            if (is_atom) g_proj_h[t * H_ + hc] = __float2half(v + b_in[hc]);
            else         g_proj_h[(NATOM + t) * H_ + hc] = __float2half(v);
        }
    }
}

// ---------------------------------------------------------------------------
// Kernel 2: per-molecule mean of relu(A_proj[af] + F_proj[fp]).  (R12 form)
// Grid 512 x 256: 2 molecules/block, 8 warps, 32 atoms/warp. PDL: index LDGs
// issue before cudaGridDependencySynchronize(); gathers run after proj done.
// ---------------------------------------------------------------------------
__global__ __launch_bounds__(256, 8)
void mol_kernel(const int* __restrict__ atom_features,
                const int* __restrict__ fingerprints) {
    __shared__ __align__(16) float s_part[8 * H_];

    const int tid  = threadIdx.x;
    const int w    = tid >> 5;                            // 0..7
    const int lane = tid & 31;
    const int ml   = w >> 2;                              // molecule-in-block 0..1
    const int q    = w & 3;                               // atom quarter
    const int bm   = blockIdx.x * 2 + ml;

    // Pre-dependency work: index loads are independent of proj's output.
    const int abase = bm * A_ + q * 32 + lane;
    const int ra = atom_features[abase] * (H_ / 4);       // uint2-row base
    const int rf = (NATOM + fingerprints[abase]) * (H_ / 4);

    // Wait for proj_kernel's memory (no-op under plain serialized launch).
    cudaGridDependencySynchronize();

    const uint2* __restrict__ gp = (const uint2*)g_proj_h;
    const __half2 zero2 = __float2half2_rn(0.0f);

    float4 acc = make_float4(0.0f, 0.0f, 0.0f, 0.0f);
    #pragma unroll 8
    for (int a = 0; a < 32; a++) {
        int ia = __shfl_sync(0xFFFFFFFFu, ra, a);
        int If = __shfl_sync(0xFFFFFFFFu, rf, a);
        uint2 ua = gp[ia + lane];
        uint2 uf = gp[If + lane];
        __half2 va0 = *(__half2*)&ua.x, va1 = *(__half2*)&ua.y;
        __half2 vf0 = *(__half2*)&uf.x, vf1 = *(__half2*)&uf.y;
        __half2 s0 = __hmax2(__hadd2(va0, vf0), zero2);
        __half2 s1 = __hmax2(__hadd2(va1, vf1), zero2);
        float2 p0 = __half22float2(s0);
        float2 p1 = __half22float2(s1);
        acc.x += p0.x; acc.y += p0.y; acc.z += p1.x; acc.w += p1.y;
    }
    ((float4*)s_part)[w * 32 + lane] = acc;               // STS.128, conflict-free
    __syncthreads();

    {
        int m = tid >> 7, d = tid & 127;
        float v = (s_part[(4 * m + 0) * H_ + d] + s_part[(4 * m + 1) * H_ + d] +
                   s_part[(4 * m + 2) * H_ + d] + s_part[(4 * m + 3) * H_ + d])
                  * (1.0f / (float)A_);
        g_mol[(blockIdx.x * 2 + m) * H_ + d] = v;
    }
}

// ---------------------------------------------------------------------------
// Kernel 3: mixing weights + phys mix + LayerNorm + 2-layer MLP head. (R12)
// One block per batch item; 256 threads (W1 GEMV 2-way K-split). PDL: ratio
// normalization runs pre-dependency; g_mol reads after the sync.
// ---------------------------------------------------------------------------
__global__ __launch_bounds__(256)
void head_kernel(const float* __restrict__ phys,
                 const float* __restrict__ ratios,
                 const float* __restrict__ ln_g,
                 const float* __restrict__ ln_b,
                 const float* __restrict__ W1,
                 const float* __restrict__ b1,
                 const float* __restrict__ W2,
                 const float* __restrict__ b2,
                 float* __restrict__ out) {
    const int b   = blockIdx.x;
    const int tid = threadIdx.x;
    const int h   = tid & 127;
    const int ks  = tid >> 7;          // 0,1: K-split of the W1 GEMV

    __shared__ float s_w[M_];
    __shared__ float s_z[H_ + P_];
    __shared__ float s_zn[H_ + P_];
    __shared__ float s_red[8];
    __shared__ float s_t[2][H_];

    // Pre-dependency work: ratios are an input, independent of mol's output.
    if (tid < M_) s_w[tid] = ratios[b * M_ + tid];
    __syncthreads();
    if (tid == 0) {
        float s = 0.0f;
        #pragma unroll
        for (int m = 0; m < M_; m++) s += s_w[m];
        float inv = 1.0f / (s + 1e-8f);
        #pragma unroll
        for (int m = 0; m < M_; m++) s_w[m] *= inv;
    }
    __syncthreads();

    // Wait for mol_kernel's g_mol (no-op under plain serialized launch).
    cudaGridDependencySynchronize();

    if (tid < H_) {
        float acc = 0.0f;
        #pragma unroll
        for (int m = 0; m < M_; m++) acc += s_w[m] * g_mol[(b * M_ + m) * H_ + tid];
        s_z[tid] = acc;
        if (tid < P_) {
            float accp = 0.0f;
            #pragma unroll
            for (int m = 0; m < M_; m++) {
                float v = phys[(b * M_ + m) * P_ + tid];
                if (v != v) v = 0.0f;
                else if (isinf(v)) v = (v > 0.0f) ? 1000.0f : -1000.0f;
                accp += s_w[m] * v;
            }
            s_z[H_ + tid] = accp;
        }
    }
    __syncthreads();

    if (tid < H_) {
        float x  = s_z[tid];
        float x2 = x * x;
        if (tid < P_) { float e = s_z[H_ + tid]; x += e; x2 += e * e; }
        #pragma unroll
        for (int o = 16; o > 0; o >>= 1) {
            x  += __shfl_xor_sync(0xFFFFFFFFu, x,  o);
            x2 += __shfl_xor_sync(0xFFFFFFFFu, x2, o);
        }
        int warp = tid >> 5;
        if ((tid & 31) == 0) { s_red[warp] = x; s_red[4 + warp] = x2; }
    }
    __syncthreads();

    if (tid < H_) {
        float sum  = s_red[0] + s_red[1] + s_red[2] + s_red[3];
        float sum2 = s_red[4] + s_red[5] + s_red[6] + s_red[7];
        const float N = (float)(H_ + P_);
        float mu  = sum / N;
        float var = sum2 / N - mu * mu;
        float rstd = rsqrtf(var + 1e-5f);
        s_zn[tid] = (s_z[tid] - mu) * rstd * ln_g[tid] + ln_b[tid];
        if (tid < P_) s_zn[H_ + tid] = (s_z[H_ + tid] - mu) * rstd * ln_g[H_ + tid] + ln_b[H_ + tid];
    }
    __syncthreads();

    // W1 GEMV, 2-way K-split: ks=0 -> d in [0,72), ks=1 -> d in [72,144)
    {
        float t = (ks == 0) ? b1[h] : 0.0f;
        const int dlo = ks * 72;
        #pragma unroll 8
        for (int d = 0; d < 72; d++) t += s_zn[dlo + d] * W1[(dlo + d) * H_ + h];
        s_t[ks][h] = t;
    }
    __syncthreads();

    if (tid < H_) {
        float r = fmaxf(s_t[0][tid] + s_t[1][tid], 0.0f) * W2[tid];
        #pragma unroll
        for (int o = 16; o > 0; o >>= 1) r += __shfl_xor_sync(0xFFFFFFFFu, r, o);
        int warp = tid >> 5;
        if ((tid & 31) == 0) s_red[warp] = r;
    }
    __syncthreads();
    if (tid == 0) {
        float y = s_red[0] + s_red[1] + s_red[2] + s_red[3] + b2[0];
        if (y != y) y = 0.0f;
        else if (isinf(y)) y = (y > 0.0f) ? 3.4028234663852886e38f : -3.4028234663852886e38f;
        out[b] = y;
    }
}

// Launch helper: PDL (programmatic dependent launch) with plain-launch fallback.
template <typename... Args>
static void launch_pdl(void (*kern)(Args...), dim3 grid, dim3 block,
                       Args... args) {
    cudaLaunchConfig_t cfg = {};
    cfg.gridDim = grid;
    cfg.blockDim = block;
    cfg.dynamicSmemBytes = 0;
    cudaLaunchAttribute attr[1];
    attr[0].id = cudaLaunchAttributeProgrammaticStreamSerialization;
    attr[0].val.programmaticStreamSerializationAllowed = 1;
    cfg.attrs = attr;
    cfg.numAttrs = 1;
    cudaError_t err = cudaLaunchKernelEx(&cfg, kern, args...);
    if (err != cudaSuccess) {
        (void)cudaGetLastError();                 // clear; fall back to plain launch
        cfg.attrs = nullptr;
        cfg.numAttrs = 0;
        cudaLaunchKernelEx(&cfg, kern, args...);
    }
}

extern "C" void kernel_launch(void* const* d_in, const int* in_sizes, int n_in,
                              void* d_out, int out_size) {
    const int*   atom_features = (const int*)  d_in[0];
    const int*   fingerprints  = (const int*)  d_in[1];
    const float* phys          = (const float*)d_in[2];
    const float* ratios        = (const float*)d_in[3];
    const float* atom_emb      = (const float*)d_in[4];
    const float* fp_emb        = (const float*)d_in[5];
    const float* W_in          = (const float*)d_in[6];
    const float* b_in          = (const float*)d_in[7];
    const float* ln_g          = (const float*)d_in[8];
    const float* ln_b          = (const float*)d_in[9];
    const float* W1            = (const float*)d_in[10];
    const float* b1            = (const float*)d_in[11];
    const float* W2            = (const float*)d_in[12];
    const float* b2            = (const float*)d_in[13];
    float* out = (float*)d_out;

    static int smem_configured = 0;
    if (!smem_configured) {
        cudaFuncSetAttribute(proj_kernel,
                             cudaFuncAttributeMaxDynamicSharedMemorySize,
                             PROJ_SMEM_BYTES);
        smem_configured = 1;
    }

    proj_kernel<<<PROJ_GRID, 1024, PROJ_SMEM_BYTES>>>(atom_emb, fp_emb, W_in, b_in);
    launch_pdl(mol_kernel, dim3(512), dim3(256), atom_features, fingerprints);
    launch_pdl(head_kernel, dim3(B_), dim3(256), phys, ratios, ln_g, ln_b,
               W1, b1, W2, b2, out);
}

// round 17
// speedup vs baseline: 1.5000x; 1.0274x over previous
#include <cuda_runtime.h>
#include <cuda_fp16.h>
#include <math.h>

#define B_  64
#define M_  16
#define A_  128
#define H_  128
#define P_  16
#define NATOM 100
#define NFP   2048
#define NTAB  (NATOM + NFP)     // 2148
#define RPB   16                // table rows per block in proj kernel
#define PROJ_GRID 135           // 7 atom blocks + 128 fp blocks (one wave)

// proj dynamic smem (floats): s_W 64KB | s_eT 8KB | s_p 32KB
#define PROJ_SMEM_BYTES (26624 * 4)
// head dynamic smem: W1 staged (144*128 floats = 72 KB)
#define HEAD_SMEM_BYTES ((H_ + P_) * H_ * 4)

// Scratch (__device__ globals: allocation-free rule)
__device__ __half g_proj_h[NTAB * H_];    // projected tables, fp16 (0.55 MB, L2-resident)
__device__ float  g_mol[B_ * M_ * H_];    // per-molecule mean embeddings

// ---------------------------------------------------------------------------
// Kernel 1: projected tables -> g_proj_h (fp16).  (R12 compute — best measured)
// Adds cudaTriggerProgrammaticLaunchCompletion after the final store.
// ---------------------------------------------------------------------------
__global__ __launch_bounds__(1024, 1)
void proj_kernel(const float* __restrict__ atom_emb,
                 const float* __restrict__ fp_emb,
                 const float* __restrict__ W_in,
                 const float* __restrict__ b_in) {
    extern __shared__ __align__(16) float smem[];
    float* s_W  = smem;              // [d][h] 128x128
    float* s_eT = smem + 16384;      // [d][r] stride 16
    float* s_p  = smem + 18432;      // [ks][r][h]

    const int tid = threadIdx.x;
    const int blk = blockIdx.x;
    const int h  = tid & 127;
    const int ks = (tid >> 7) & 3;
    const int rh = tid >> 9;
    const int r0 = rh * 8;
    const bool is_atom = (blk < 7);
    const int lrow0 = is_atom ? blk * RPB : (blk - 7) * RPB;
    const int nrows = is_atom ? NATOM : NFP;
    const float* __restrict__ Whalf = W_in + (is_atom ? 0 : H_ * H_);

    #pragma unroll
    for (int i = tid; i < 4096; i += 1024)
        ((float4*)s_W)[i] = ((const float4*)Whalf)[i];

    #pragma unroll
    for (int i = tid; i < RPB * H_; i += 1024) {
        int r = i >> 7, d = i & 127;
        int t = lrow0 + r;
        float v = 0.0f;
        if (t < nrows) v = is_atom ? atom_emb[t * H_ + d] : fp_emb[t * H_ + d];
        s_eT[d * 16 + r] = v;
    }
    __syncthreads();

    const int d0 = ks * 32;
    float acc[8];
    #pragma unroll
    for (int r = 0; r < 8; r++) acc[r] = 0.0f;

    #pragma unroll 8
    for (int dd = 0; dd < 32; dd++) {
        const int d = d0 + dd;
        const float w = s_W[d * H_ + h];                  // LDS.32, conflict-free
        const float* e = s_eT + d * 16 + r0;              // broadcast
        const float4 e0 = *(const float4*)(e);
        const float4 e1 = *(const float4*)(e + 4);
        acc[0] += e0.x * w; acc[1] += e0.y * w; acc[2] += e0.z * w; acc[3] += e0.w * w;
        acc[4] += e1.x * w; acc[5] += e1.y * w; acc[6] += e1.z * w; acc[7] += e1.w * w;
    }

    #pragma unroll
    for (int r = 0; r < 8; r++) s_p[(ks * RPB + r0 + r) * H_ + h] = acc[r];
    __syncthreads();

    const int NP = RPB * H_;
    #pragma unroll
    for (int i = tid; i < NP; i += 1024) {
        int r = i >> 7, hc = i & 127;
        int t = lrow0 + r;
        if (t < nrows) {
            float v = s_p[i] + s_p[NP + i] + s_p[2 * NP + i] + s_p[3 * NP + i];
            if (is_atom) g_proj_h[t * H_ + hc] = __float2half(v + b_in[hc]);
            else         g_proj_h[(NATOM + t) * H_ + hc] = __float2half(v);
        }
    }
    // Let mol's grid launch while this grid drains.
    cudaTriggerProgrammaticLaunchCompletion();
}

// ---------------------------------------------------------------------------
// Kernel 2: per-molecule mean of relu(A_proj[af] + F_proj[fp]).  (R12 compute)
// PDL: index LDGs pre-dependency; trigger after final g_mol store.
// ---------------------------------------------------------------------------
__global__ __launch_bounds__(256, 8)
void mol_kernel(const int* __restrict__ atom_features,
                const int* __restrict__ fingerprints) {
    __shared__ __align__(16) float s_part[8 * H_];

    const int tid  = threadIdx.x;
    const int w    = tid >> 5;                            // 0..7
    const int lane = tid & 31;
    const int ml   = w >> 2;                              // molecule-in-block 0..1
    const int q    = w & 3;                               // atom quarter
    const int bm   = blockIdx.x * 2 + ml;

    // Pre-dependency: index loads are independent of proj's output.
    const int abase = bm * A_ + q * 32 + lane;
    const int ra = atom_features[abase] * (H_ / 4);       // uint2-row base
    const int rf = (NATOM + fingerprints[abase]) * (H_ / 4);

    cudaGridDependencySynchronize();                      // wait for proj memory

    const uint2* __restrict__ gp = (const uint2*)g_proj_h;
    const __half2 zero2 = __float2half2_rn(0.0f);

    float4 acc = make_float4(0.0f, 0.0f, 0.0f, 0.0f);
    #pragma unroll 8
    for (int a = 0; a < 32; a++) {
        int ia = __shfl_sync(0xFFFFFFFFu, ra, a);
        int If = __shfl_sync(0xFFFFFFFFu, rf, a);
        uint2 ua = gp[ia + lane];
        uint2 uf = gp[If + lane];
        __half2 va0 = *(__half2*)&ua.x, va1 = *(__half2*)&ua.y;
        __half2 vf0 = *(__half2*)&uf.x, vf1 = *(__half2*)&uf.y;
        __half2 s0 = __hmax2(__hadd2(va0, vf0), zero2);
        __half2 s1 = __hmax2(__hadd2(va1, vf1), zero2);
        float2 p0 = __half22float2(s0);
        float2 p1 = __half22float2(s1);
        acc.x += p0.x; acc.y += p0.y; acc.z += p1.x; acc.w += p1.y;
    }
    ((float4*)s_part)[w * 32 + lane] = acc;               // STS.128, conflict-free
    __syncthreads();

    {
        int m = tid >> 7, d = tid & 127;
        float v = (s_part[(4 * m + 0) * H_ + d] + s_part[(4 * m + 1) * H_ + d] +
                   s_part[(4 * m + 2) * H_ + d] + s_part[(4 * m + 3) * H_ + d])
                  * (1.0f / (float)A_);
        g_mol[(blockIdx.x * 2 + m) * H_ + d] = v;
    }
    cudaTriggerProgrammaticLaunchCompletion();
}

// ---------------------------------------------------------------------------
// Kernel 3: mixing weights + phys mix + LayerNorm + 2-layer MLP head.
// One block per batch item; 256 threads. PDL: ratios normalize AND W1 stages
// into smem pre-dependency (overlapped with mol); GEMV runs from LDS.
// ---------------------------------------------------------------------------
__global__ __launch_bounds__(256)
void head_kernel(const float* __restrict__ phys,
                 const float* __restrict__ ratios,
                 const float* __restrict__ ln_g,
                 const float* __restrict__ ln_b,
                 const float* __restrict__ W1,
                 const float* __restrict__ b1,
                 const float* __restrict__ W2,
                 const float* __restrict__ b2,
                 float* __restrict__ out) {
    extern __shared__ __align__(16) float s_W1[];         // [(H+P)][H] 72 KB

    const int b   = blockIdx.x;
    const int tid = threadIdx.x;
    const int h   = tid & 127;
    const int ks  = tid >> 7;          // 0,1: K-split of the W1 GEMV

    __shared__ float s_w[M_];
    __shared__ float s_z[H_ + P_];
    __shared__ float s_zn[H_ + P_];
    __shared__ float s_red[8];
    __shared__ float s_t[2][H_];

    // ---- Pre-dependency work (overlaps with mol_kernel) ----
    // Stage W1: 18432 floats = 4608 float4 / 256 threads = 18 each, coalesced.
    #pragma unroll
    for (int i = tid; i < ((H_ + P_) * H_) / 4; i += 256)
        ((float4*)s_W1)[i] = ((const float4*)W1)[i];

    if (tid < M_) s_w[tid] = ratios[b * M_ + tid];
    __syncthreads();
    if (tid == 0) {
        float s = 0.0f;
        #pragma unroll
        for (int m = 0; m < M_; m++) s += s_w[m];
        float inv = 1.0f / (s + 1e-8f);
        #pragma unroll
        for (int m = 0; m < M_; m++) s_w[m] *= inv;
    }
    __syncthreads();

    cudaGridDependencySynchronize();                      // wait for g_mol

    if (tid < H_) {
        float acc = 0.0f;
        #pragma unroll
        for (int m = 0; m < M_; m++) acc += s_w[m] * g_mol[(b * M_ + m) * H_ + tid];
        s_z[tid] = acc;
        if (tid < P_) {
            float accp = 0.0f;
            #pragma unroll
            for (int m = 0; m < M_; m++) {
                float v = phys[(b * M_ + m) * P_ + tid];
                if (v != v) v = 0.0f;
                else if (isinf(v)) v = (v > 0.0f) ? 1000.0f : -1000.0f;
                accp += s_w[m] * v;
            }
            s_z[H_ + tid] = accp;
        }
    }
    __syncthreads();

    if (tid < H_) {
        float x  = s_z[tid];
        float x2 = x * x;
        if (tid < P_) { float e = s_z[H_ + tid]; x += e; x2 += e * e; }
        #pragma unroll
        for (int o = 16; o > 0; o >>= 1) {
            x  += __shfl_xor_sync(0xFFFFFFFFu, x,  o);
            x2 += __shfl_xor_sync(0xFFFFFFFFu, x2, o);
        }
        int warp = tid >> 5;
        if ((tid & 31) == 0) { s_red[warp] = x; s_red[4 + warp] = x2; }
    }
    __syncthreads();

    if (tid < H_) {
        float sum  = s_red[0] + s_red[1] + s_red[2] + s_red[3];
        float sum2 = s_red[4] + s_red[5] + s_red[6] + s_red[7];
        const float N = (float)(H_ + P_);
        float mu  = sum / N;
        float var = sum2 / N - mu * mu;
        float rstd = rsqrtf(var + 1e-5f);
        s_zn[tid] = (s_z[tid] - mu) * rstd * ln_g[tid] + ln_b[tid];
        if (tid < P_) s_zn[H_ + tid] = (s_z[H_ + tid] - mu) * rstd * ln_g[H_ + tid] + ln_b[H_ + tid];
    }
    __syncthreads();

    // W1 GEMV from smem, 2-way K-split: ks=0 -> [0,72), ks=1 -> [72,144)
    {
        float t = (ks == 0) ? b1[h] : 0.0f;
        const int dlo = ks * 72;
        #pragma unroll 8
        for (int d = 0; d < 72; d++) t += s_zn[dlo + d] * s_W1[(dlo + d) * H_ + h];
        s_t[ks][h] = t;
    }
    __syncthreads();

    if (tid < H_) {
        float r = fmaxf(s_t[0][tid] + s_t[1][tid], 0.0f) * W2[tid];
        #pragma unroll
        for (int o = 16; o > 0; o >>= 1) r += __shfl_xor_sync(0xFFFFFFFFu, r, o);
        int warp = tid >> 5;
        if ((tid & 31) == 0) s_red[warp] = r;
    }
    __syncthreads();
    if (tid == 0) {
        float y = s_red[0] + s_red[1] + s_red[2] + s_red[3] + b2[0];
        if (y != y) y = 0.0f;
        else if (isinf(y)) y = (y > 0.0f) ? 3.4028234663852886e38f : -3.4028234663852886e38f;
        out[b] = y;
    }
}

// Launch helper: PDL with plain-launch fallback.
template <typename... Args>
static void launch_pdl(void (*kern)(Args...), dim3 grid, dim3 block,
                       size_t smem, Args... args) {
    cudaLaunchConfig_t cfg = {};
    cfg.gridDim = grid;
    cfg.blockDim = block;
    cfg.dynamicSmemBytes = smem;
    cudaLaunchAttribute attr[1];
    attr[0].id = cudaLaunchAttributeProgrammaticStreamSerialization;
    attr[0].val.programmaticStreamSerializationAllowed = 1;
    cfg.attrs = attr;
    cfg.numAttrs = 1;
    cudaError_t err = cudaLaunchKernelEx(&cfg, kern, args...);
    if (err != cudaSuccess) {
        (void)cudaGetLastError();                 // clear; fall back to plain launch
        cfg.attrs = nullptr;
        cfg.numAttrs = 0;
        cudaLaunchKernelEx(&cfg, kern, args...);
    }
}

extern "C" void kernel_launch(void* const* d_in, const int* in_sizes, int n_in,
                              void* d_out, int out_size) {
    const int*   atom_features = (const int*)  d_in[0];
    const int*   fingerprints  = (const int*)  d_in[1];
    const float* phys          = (const float*)d_in[2];
    const float* ratios        = (const float*)d_in[3];
    const float* atom_emb      = (const float*)d_in[4];
    const float* fp_emb        = (const float*)d_in[5];
    const float* W_in          = (const float*)d_in[6];
    const float* b_in          = (const float*)d_in[7];
    const float* ln_g          = (const float*)d_in[8];
    const float* ln_b          = (const float*)d_in[9];
    const float* W1            = (const float*)d_in[10];
    const float* b1            = (const float*)d_in[11];
    const float* W2            = (const float*)d_in[12];
    const float* b2            = (const float*)d_in[13];
    float* out = (float*)d_out;

    static int smem_configured = 0;
    if (!smem_configured) {
        cudaFuncSetAttribute(proj_kernel,
                             cudaFuncAttributeMaxDynamicSharedMemorySize,
                             PROJ_SMEM_BYTES);
        cudaFuncSetAttribute(head_kernel,
                             cudaFuncAttributeMaxDynamicSharedMemorySize,
                             HEAD_SMEM_BYTES);
        smem_configured = 1;
    }

    proj_kernel<<<PROJ_GRID, 1024, PROJ_SMEM_BYTES>>>(atom_emb, fp_emb, W_in, b_in);
    launch_pdl(mol_kernel, dim3(512), dim3(256), (size_t)0,
               atom_features, fingerprints);
    launch_pdl(head_kernel, dim3(B_), dim3(256), (size_t)HEAD_SMEM_BYTES,
               phys, ratios, ln_g, ln_b, W1, b1, W2, b2, out);
}